// round 3
// baseline (speedup 1.0000x reference)
#include <cuda_runtime.h>
#include <cuda_bf16.h>
#include <cstddef>

#define Bn 4
#define Cn 256
#define Ln 8000
#define CRn 64
#define Kn 7
#define Nn 24
#define EPSf 1e-5f

// ---------------- scratch (device globals; no allocation allowed) ----------
__device__ float g_buf0[(size_t)Bn * Cn * Ln];
__device__ float g_buf1[(size_t)Bn * Cn * Ln];
__device__ float g_h[(size_t)Bn * Cn * Ln];
__device__ float g_skip[(size_t)Bn * Cn * Ln];
__device__ float g_kern[(size_t)Bn * Kn * Ln];
__device__ float g_tmp[(size_t)Bn * Cn * Ln];

// ---------------- zero ------------------------------------------------------
__global__ void zero_kernel(float* p, size_t n) {
    size_t i = (size_t)blockIdx.x * blockDim.x + threadIdx.x;
    if (i < n) p[i] = 0.f;
}

// ---------------- channel LayerNorm (over C) --------------------------------
// grid (L/32, B), 256 threads: j = t&31 (position), cg = t>>5 (8 channel groups)
__global__ __launch_bounds__(256) void ln_kernel(
    const float* __restrict__ x, const float* __restrict__ g,
    const float* __restrict__ bta, float* __restrict__ y)
{
    int b = blockIdx.y, lbase = blockIdx.x * 32;
    int t = threadIdx.x, j = t & 31, cg = t >> 5;
    __shared__ float vs[Cn][32];
    __shared__ float psum[8][32], psq[8][32];
    __shared__ float mres[32], rres[32];

    const float* xb = x + ((size_t)b * Cn) * Ln + lbase;
    float s = 0.f, sq = 0.f;
#pragma unroll 4
    for (int i = 0; i < 32; i++) {
        int c = cg * 32 + i;
        float v = xb[(size_t)c * Ln + j];
        vs[c][j] = v; s += v; sq += v * v;
    }
    psum[cg][j] = s; psq[cg][j] = sq;
    __syncthreads();
    if (t < 32) {
        float S = 0.f, Q = 0.f;
#pragma unroll
        for (int i = 0; i < 8; i++) { S += psum[i][t]; Q += psq[i][t]; }
        float m = S * (1.f / Cn);
        float var = Q * (1.f / Cn) - m * m;
        mres[t] = m; rres[t] = rsqrtf(var + EPSf);
    }
    __syncthreads();
    float m = mres[j], r = rres[j];
    float* yb = y + ((size_t)b * Cn) * Ln + lbase;
#pragma unroll 4
    for (int i = 0; i < 32; i++) {
        int c = cg * 32 + i;
        yb[(size_t)c * Ln + j] = (vs[c][j] - m) * r * g[c] + bta[c];
    }
}

// ---------------- involution kernel generator: kern = Ws @ relu(Wr @ out) ---
// grid (L/32, B), 256 threads
__global__ __launch_bounds__(256) void kern_kernel(
    const float* __restrict__ out, const float* __restrict__ wr,
    const float* __restrict__ ws, float* __restrict__ kern)
{
    int b = blockIdx.y, lbase = blockIdx.x * 32;
    int t = threadIdx.x;
    __shared__ float os[Cn][32];
    __shared__ float rs[CRn][33];

    const float* ob = out + ((size_t)b * Cn) * Ln + lbase;
    {
        int j = t & 31, cg = t >> 5;
#pragma unroll 4
        for (int i = 0; i < 32; i++) { int c = cg * 32 + i; os[c][j] = ob[(size_t)c * Ln + j]; }
    }
    __syncthreads();

    // red[r][j] for r = t>>2 (64 rows), j in [jg*8, jg*8+8)
    int r = t >> 2, jg = t & 3;
    float acc[8];
#pragma unroll
    for (int i = 0; i < 8; i++) acc[i] = 0.f;
    const float* wrr = wr + (size_t)r * Cn;
#pragma unroll 8
    for (int c = 0; c < Cn; c++) {
        float w = __ldg(&wrr[c]);
#pragma unroll
        for (int i = 0; i < 8; i++) acc[i] += w * os[c][jg * 8 + i];
    }
#pragma unroll
    for (int i = 0; i < 8; i++) rs[r][jg * 8 + i] = fmaxf(acc[i], 0.f);
    __syncthreads();

    // kern[k][j]: first 224 threads
    if (t < Kn * 32) {
        int k = t >> 5, j = t & 31;
        float a = 0.f;
        const float* wsk = ws + (size_t)k * CRn;
#pragma unroll 8
        for (int r2 = 0; r2 < CRn; r2++) a += __ldg(&wsk[r2]) * rs[r2][j];
        kern[((size_t)b * Kn + k) * Ln + lbase + j] = a;
    }
}

// ---------------- involution apply + PReLU + channel LN ---------------------
// grid (L/32, B), 256 threads
__global__ __launch_bounds__(256) void invo_kernel(
    const float* __restrict__ out, const float* __restrict__ kern,
    const float* __restrict__ pa, const float* __restrict__ g,
    const float* __restrict__ bta, int dil, float* __restrict__ h)
{
    int b = blockIdx.y, lbase = blockIdx.x * 32;
    int t = threadIdx.x, j = t & 31, cg = t >> 5;
    __shared__ float ks[Kn][32];
    __shared__ float hs[Cn][32];
    __shared__ float psum[8][32], psq[8][32], mres[32], rres[32];

    if (t < Kn * 32) {
        int k = t >> 5;
        ks[k][t & 31] = kern[((size_t)b * Kn + k) * Ln + lbase + (t & 31)];
    }
    __syncthreads();

    float a = *pa;
    const float* ob = out + ((size_t)b * Cn) * Ln;
    int l = lbase + j;
    float s = 0.f, sq = 0.f;
#pragma unroll 2
    for (int i = 0; i < 32; i++) {
        int c = cg * 32 + i;
        const float* oc = ob + (size_t)c * Ln;
        float acc = 0.f;
#pragma unroll
        for (int k = 0; k < Kn; k++) {
            int ll = l + (k - 3) * dil;
            float v = (ll >= 0 && ll < Ln) ? oc[ll] : 0.f;
            acc += v * ks[k][j];
        }
        acc = acc >= 0.f ? acc : a * acc;
        hs[c][j] = acc; s += acc; sq += acc * acc;
    }
    psum[cg][j] = s; psq[cg][j] = sq;
    __syncthreads();
    if (t < 32) {
        float S = 0.f, Q = 0.f;
#pragma unroll
        for (int i = 0; i < 8; i++) { S += psum[i][t]; Q += psq[i][t]; }
        float m = S * (1.f / Cn);
        mres[t] = m; rres[t] = rsqrtf(Q * (1.f / Cn) - m * m + EPSf);
    }
    __syncthreads();
    float m = mres[j], rr = rres[j];
    float* hb = h + ((size_t)b * Cn) * Ln + lbase;
#pragma unroll 4
    for (int i = 0; i < 32; i++) {
        int c = cg * 32 + i;
        hb[(size_t)c * Ln + j] = (hs[c][j] - m) * rr * g[c] + bta[c];
    }
}

// ---------------- generic 256x256 1x1-conv GEMM -----------------------------
// Y[o, l] = sum_c W[o,c] * X[c, l]  (+mode extras), tile 256 x 64 positions.
// grid (L/64, B), 256 threads; per-thread 8x8 register tile.
// mode 0: Y = WX       mode 1: Y = WX + R
// mode 2: Y += WX      mode 3: Y = relu(W @ prelu(X, *pa))
__global__ __launch_bounds__(256) void gemm_kernel(
    const float* __restrict__ W, const float* __restrict__ X,
    const float* __restrict__ R, float* __restrict__ Y,
    const float* __restrict__ pa, int mode)
{
    int b = blockIdx.y, lbase = blockIdx.x * 64;
    int t = threadIdx.x;
    __shared__ float Ws[Cn * 33];   // 256 rows x 32 cols chunk, row stride 33 (bank-safe)
    __shared__ float Xs[32][64];    // 32 c x 64 l chunk

    int orow = t >> 3;          // 0..31  -> o = orow + i*32
    int jb = (t & 7) * 8;       // 0..56  -> j = jb + jj

    float acc[8][8];
#pragma unroll
    for (int i = 0; i < 8; i++)
#pragma unroll
        for (int jj = 0; jj < 8; jj++) acc[i][jj] = 0.f;

    const float* Xb = X + ((size_t)b * Cn) * Ln + lbase;
    float aP = (mode == 3) ? *pa : 0.f;

    for (int cc = 0; cc < Cn; cc += 32) {
        // stage W chunk: 256 rows x 32 cols = 2048 float4, 8 per thread (FIXED)
#pragma unroll
        for (int m = 0; m < 8; m++) {
            int e4 = m * 256 + t;          // float4 index, 0..2047
            int o = e4 >> 3;               // 8 float4 per row
            int u4 = (e4 & 7) * 4;         // col within 32-wide chunk
            float4 v = *(const float4*)&W[(size_t)o * Cn + cc + u4];
            Ws[o * 33 + u4 + 0] = v.x;
            Ws[o * 33 + u4 + 1] = v.y;
            Ws[o * 33 + u4 + 2] = v.z;
            Ws[o * 33 + u4 + 3] = v.w;
        }
        // stage X chunk (coalesced float4): 32x64
#pragma unroll
        for (int m = 0; m < 2; m++) {
            int e = m * 256 + t;
            int row = e >> 4, col = (e & 15) * 4;
            float4 v = *(const float4*)&Xb[(size_t)(cc + row) * Ln + col];
            if (mode == 3) {
                v.x = v.x >= 0.f ? v.x : aP * v.x;
                v.y = v.y >= 0.f ? v.y : aP * v.y;
                v.z = v.z >= 0.f ? v.z : aP * v.z;
                v.w = v.w >= 0.f ? v.w : aP * v.w;
            }
            *(float4*)&Xs[row][col] = v;
        }
        __syncthreads();

#pragma unroll 8
        for (int u = 0; u < 32; u++) {
            float xr[8];
            float4 x0 = *(float4*)&Xs[u][jb];
            float4 x1 = *(float4*)&Xs[u][jb + 4];
            xr[0] = x0.x; xr[1] = x0.y; xr[2] = x0.z; xr[3] = x0.w;
            xr[4] = x1.x; xr[5] = x1.y; xr[6] = x1.z; xr[7] = x1.w;
#pragma unroll
            for (int i = 0; i < 8; i++) {
                float w = Ws[(orow + i * 32) * 33 + u];
#pragma unroll
                for (int jj = 0; jj < 8; jj++) acc[i][jj] += w * xr[jj];
            }
        }
        __syncthreads();
    }

    float* Yb = Y + ((size_t)b * Cn) * Ln + lbase;
    const float* Rb = (mode == 1) ? R + ((size_t)b * Cn) * Ln + lbase : nullptr;
#pragma unroll
    for (int i = 0; i < 8; i++) {
        int o = orow + i * 32;
        float* yp = &Yb[(size_t)o * Ln + jb];
#pragma unroll
        for (int jj = 0; jj < 8; jj++) {
            float v = acc[i][jj];
            if (mode == 1)      v += Rb[(size_t)o * Ln + jb + jj];
            else if (mode == 2) v += yp[jj];
            else if (mode == 3) v = fmaxf(v, 0.f);
            yp[jj] = v;
        }
    }
}

// ---------------- launcher ---------------------------------------------------
extern "C" void kernel_launch(void* const* d_in, const int* in_sizes, int n_in,
                              void* d_out, int out_size)
{
    const float* x           = (const float*)d_in[0];
    const float* init_ln_g   = (const float*)d_in[1];
    const float* init_ln_b   = (const float*)d_in[2];
    const float* init_conv_w = (const float*)d_in[3];
    const float* w_reduce    = (const float*)d_in[4];
    const float* w_span      = (const float*)d_in[5];
    const float* prelu_a     = (const float*)d_in[6];
    const float* ln_g        = (const float*)d_in[7];
    const float* ln_b        = (const float*)d_in[8];
    const float* conv_main_w = (const float*)d_in[9];
    const float* conv_skip_w = (const float*)d_in[10];
    const float* post_prelu  = (const float*)d_in[11];
    const float* post_conv_w = (const float*)d_in[12];

    float *buf0, *buf1, *hbuf, *skip, *kern, *tmp;
    cudaGetSymbolAddress((void**)&buf0, g_buf0);
    cudaGetSymbolAddress((void**)&buf1, g_buf1);
    cudaGetSymbolAddress((void**)&hbuf, g_h);
    cudaGetSymbolAddress((void**)&skip, g_skip);
    cudaGetSymbolAddress((void**)&kern, g_kern);
    cudaGetSymbolAddress((void**)&tmp,  g_tmp);

    dim3 g32(Ln / 32, Bn);
    dim3 g64(Ln / 64, Bn);
    size_t nelem = (size_t)Bn * Cn * Ln;

    // init: LN + init conv
    ln_kernel<<<g32, 256>>>(x, init_ln_g, init_ln_b, tmp);
    gemm_kernel<<<g64, 256>>>(init_conv_w, tmp, nullptr, buf0, nullptr, 0);
    zero_kernel<<<(int)((nelem + 1023) / 1024), 1024>>>(skip, nelem);

    float* out  = buf0;
    float* outn = buf1;
    for (int i = 0; i < Nn; i++) {
        int d = 1 << (i & 7);
        kern_kernel<<<g32, 256>>>(out, w_reduce + (size_t)i * CRn * Cn,
                                  w_span + (size_t)i * Kn * CRn, kern);
        invo_kernel<<<g32, 256>>>(out, kern, prelu_a + i,
                                  ln_g + (size_t)i * Cn, ln_b + (size_t)i * Cn, d, hbuf);
        gemm_kernel<<<g64, 256>>>(conv_main_w + (size_t)i * Cn * Cn, hbuf, out, outn, nullptr, 1);
        gemm_kernel<<<g64, 256>>>(conv_skip_w + (size_t)i * Cn * Cn, hbuf, nullptr, skip, nullptr, 2);
        float* tsw = out; out = outn; outn = tsw;
    }

    // post: prelu -> conv -> relu
    gemm_kernel<<<g64, 256>>>(post_conv_w, skip, nullptr, (float*)d_out, post_prelu, 3);
}

// round 6
// speedup vs baseline: 1.1590x; 1.1590x over previous
#include <cuda_runtime.h>
#include <cuda_bf16.h>
#include <cstddef>
#include <cstdint>

#define Bn 4
#define Cn 256
#define Ln 8000
#define CRn 64
#define Kn 7
#define Nn 24
#define EPSf 1e-5f

// ---------------- scratch (device globals; no allocation allowed) ----------
__device__ float g_buf0[(size_t)Bn * Cn * Ln];
__device__ float g_buf1[(size_t)Bn * Cn * Ln];
__device__ float g_h[(size_t)Bn * Cn * Ln];
__device__ float g_skip[(size_t)Bn * Cn * Ln];
__device__ float g_kern[(size_t)Bn * Kn * Ln];
__device__ float g_tmp[(size_t)Bn * Cn * Ln];

// ---------------- f32x2 helpers ---------------------------------------------
__device__ __forceinline__ unsigned long long pack_dup(float w) {
    unsigned long long r; unsigned int b = __float_as_uint(w);
    asm("mov.b64 %0, {%1, %1};" : "=l"(r) : "r"(b));
    return r;
}
__device__ __forceinline__ void fma2(unsigned long long& d,
                                     unsigned long long a, unsigned long long b) {
    asm("fma.rn.f32x2 %0, %1, %2, %3;" : "=l"(d) : "l"(a), "l"(b), "l"(d));
}
__device__ __forceinline__ float2 up2(unsigned long long v) {
    unsigned int lo, hi;
    asm("mov.b64 {%0, %1}, %2;" : "=r"(lo), "=r"(hi) : "l"(v));
    return make_float2(__uint_as_float(lo), __uint_as_float(hi));
}

// ---------------- zero ------------------------------------------------------
__global__ void zero_kernel(float* p, size_t n) {
    size_t i = (size_t)blockIdx.x * blockDim.x + threadIdx.x;
    if (i < n) p[i] = 0.f;
}

// ---------------- channel LayerNorm (over C) --------------------------------
__global__ __launch_bounds__(256) void ln_kernel(
    const float* __restrict__ x, const float* __restrict__ g,
    const float* __restrict__ bta, float* __restrict__ y)
{
    int b = blockIdx.y, lbase = blockIdx.x * 32;
    int t = threadIdx.x, j = t & 31, cg = t >> 5;
    __shared__ float vs[Cn][32];
    __shared__ float psum[8][32], psq[8][32];
    __shared__ float mres[32], rres[32];

    const float* xb = x + ((size_t)b * Cn) * Ln + lbase;
    float s = 0.f, sq = 0.f;
#pragma unroll 4
    for (int i = 0; i < 32; i++) {
        int c = cg * 32 + i;
        float v = xb[(size_t)c * Ln + j];
        vs[c][j] = v; s += v; sq += v * v;
    }
    psum[cg][j] = s; psq[cg][j] = sq;
    __syncthreads();
    if (t < 32) {
        float S = 0.f, Q = 0.f;
#pragma unroll
        for (int i = 0; i < 8; i++) { S += psum[i][t]; Q += psq[i][t]; }
        float m = S * (1.f / Cn);
        float var = Q * (1.f / Cn) - m * m;
        mres[t] = m; rres[t] = rsqrtf(var + EPSf);
    }
    __syncthreads();
    float m = mres[j], r = rres[j];
    float* yb = y + ((size_t)b * Cn) * Ln + lbase;
#pragma unroll 4
    for (int i = 0; i < 32; i++) {
        int c = cg * 32 + i;
        yb[(size_t)c * Ln + j] = (vs[c][j] - m) * r * g[c] + bta[c];
    }
}

// ---------------- involution kernel generator v2 ----------------------------
// kern = Ws @ relu(Wr @ out), tile 64 positions, grid (L/64, B), 256 threads.
// Per-thread reduce tile: 2 r x 8 j (4 packed f32x2 accumulators per r).
__global__ __launch_bounds__(256) void kern_kernel(
    const float* __restrict__ out, const float* __restrict__ wr,
    const float* __restrict__ ws, float* __restrict__ kern)
{
    int b = blockIdx.y, lbase = blockIdx.x * 64;
    int t = threadIdx.x;
    __shared__ float Xs[64][64];      // c-chunk x 64 positions
    __shared__ float Wr_s[64][65];    // 64 r x 64 c chunk, padded
    __shared__ float rs[64][64];      // relu'd reduce output

    int jb = (t & 7) * 8;     // 8 positions
    int rb = (t >> 3) * 2;    // 2 reduce rows

    unsigned long long acc[2][4];
#pragma unroll
    for (int i = 0; i < 2; i++)
#pragma unroll
        for (int p = 0; p < 4; p++) acc[i][p] = 0ULL;

    const float* ob = out + ((size_t)b * Cn) * Ln + lbase;

    for (int cc = 0; cc < Cn; cc += 64) {
        // stage X chunk: 64 c x 64 j, 1024 float4, 4 per thread
#pragma unroll
        for (int m = 0; m < 4; m++) {
            int e4 = m * 256 + t;
            int row = e4 >> 4, col = (e4 & 15) * 4;
            *(float4*)&Xs[row][col] =
                *(const float4*)&ob[(size_t)(cc + row) * Ln + col];
        }
        // stage Wr chunk: 64 r x 64 c
#pragma unroll
        for (int m = 0; m < 4; m++) {
            int e4 = m * 256 + t;
            int r = e4 >> 4, c4 = (e4 & 15) * 4;
            float4 v = *(const float4*)&wr[(size_t)r * Cn + cc + c4];
            Wr_s[r][c4 + 0] = v.x; Wr_s[r][c4 + 1] = v.y;
            Wr_s[r][c4 + 2] = v.z; Wr_s[r][c4 + 3] = v.w;
        }
        __syncthreads();

#pragma unroll 8
        for (int c = 0; c < 64; c++) {
            unsigned long long wp0 = pack_dup(Wr_s[rb][c]);
            unsigned long long wp1 = pack_dup(Wr_s[rb + 1][c]);
            const unsigned long long* xp =
                (const unsigned long long*)&Xs[c][jb];
            unsigned long long x0 = xp[0], x1 = xp[1], x2 = xp[2], x3 = xp[3];
            fma2(acc[0][0], wp0, x0); fma2(acc[0][1], wp0, x1);
            fma2(acc[0][2], wp0, x2); fma2(acc[0][3], wp0, x3);
            fma2(acc[1][0], wp1, x0); fma2(acc[1][1], wp1, x1);
            fma2(acc[1][2], wp1, x2); fma2(acc[1][3], wp1, x3);
        }
        __syncthreads();
    }

    // relu -> rs
#pragma unroll
    for (int i = 0; i < 2; i++)
#pragma unroll
        for (int p = 0; p < 4; p++) {
            float2 v = up2(acc[i][p]);
            rs[rb + i][jb + 2 * p]     = fmaxf(v.x, 0.f);
            rs[rb + i][jb + 2 * p + 1] = fmaxf(v.y, 0.f);
        }
    __syncthreads();

    // span: kern[k][j], 7*64 = 448 outputs
    for (int kk = t; kk < Kn * 64; kk += 256) {
        int k = kk >> 6, j = kk & 63;
        float a = 0.f;
        const float* wsk = ws + (size_t)k * CRn;
#pragma unroll 8
        for (int r2 = 0; r2 < CRn; r2++) a += wsk[r2] * rs[r2][j];
        kern[((size_t)b * Kn + k) * Ln + lbase + j] = a;
    }
}

// ---------------- involution apply + PReLU + channel LN ---------------------
__global__ __launch_bounds__(256) void invo_kernel(
    const float* __restrict__ out, const float* __restrict__ kern,
    const float* __restrict__ pa, const float* __restrict__ g,
    const float* __restrict__ bta, int dil, float* __restrict__ h)
{
    int b = blockIdx.y, lbase = blockIdx.x * 32;
    int t = threadIdx.x, j = t & 31, cg = t >> 5;
    __shared__ float ks[Kn][32];
    __shared__ float hs[Cn][32];
    __shared__ float psum[8][32], psq[8][32], mres[32], rres[32];

    if (t < Kn * 32) {
        int k = t >> 5;
        ks[k][t & 31] = kern[((size_t)b * Kn + k) * Ln + lbase + (t & 31)];
    }
    __syncthreads();

    float a = *pa;
    const float* ob = out + ((size_t)b * Cn) * Ln;
    int l = lbase + j;
    float s = 0.f, sq = 0.f;
#pragma unroll 2
    for (int i = 0; i < 32; i++) {
        int c = cg * 32 + i;
        const float* oc = ob + (size_t)c * Ln;
        float acc = 0.f;
#pragma unroll
        for (int k = 0; k < Kn; k++) {
            int ll = l + (k - 3) * dil;
            float v = (ll >= 0 && ll < Ln) ? oc[ll] : 0.f;
            acc += v * ks[k][j];
        }
        acc = acc >= 0.f ? acc : a * acc;
        hs[c][j] = acc; s += acc; sq += acc * acc;
    }
    psum[cg][j] = s; psq[cg][j] = sq;
    __syncthreads();
    if (t < 32) {
        float S = 0.f, Q = 0.f;
#pragma unroll
        for (int i = 0; i < 8; i++) { S += psum[i][t]; Q += psq[i][t]; }
        float m = S * (1.f / Cn);
        mres[t] = m; rres[t] = rsqrtf(Q * (1.f / Cn) - m * m + EPSf);
    }
    __syncthreads();
    float m = mres[j], rr = rres[j];
    float* hb = h + ((size_t)b * Cn) * Ln + lbase;
#pragma unroll 4
    for (int i = 0; i < 32; i++) {
        int c = cg * 32 + i;
        hb[(size_t)c * Ln + j] = (hs[c][j] - m) * rr * g[c] + bta[c];
    }
}

// ---------------- generic 256x256 1x1-conv GEMM (FFMA2 inner) ---------------
// Y[o, l] = sum_c W[o,c] * X[c, l]  (+mode extras), tile 256 x 64 positions.
// grid (L/64, B), 256 threads; per-thread 8x8 tile (8 rows x 4 f32x2 pairs).
// mode 0: Y = WX   1: Y = WX + R   2: Y += WX   3: Y = relu(W @ prelu(X,*pa))
__global__ __launch_bounds__(256) void gemm_kernel(
    const float* __restrict__ W, const float* __restrict__ X,
    const float* __restrict__ R, float* __restrict__ Y,
    const float* __restrict__ pa, int mode)
{
    int b = blockIdx.y, lbase = blockIdx.x * 64;
    int t = threadIdx.x;
    __shared__ float Ws[Cn * 33];   // 256 rows x 32 cols chunk, stride 33
    __shared__ float Xs[32][64];    // 32 c x 64 l chunk

    int orow = t >> 3;          // 0..31  -> o = orow + i*32
    int jb = (t & 7) * 8;       // 0..56

    unsigned long long acc[8][4];
#pragma unroll
    for (int i = 0; i < 8; i++)
#pragma unroll
        for (int p = 0; p < 4; p++) acc[i][p] = 0ULL;

    const float* Xb = X + ((size_t)b * Cn) * Ln + lbase;
    float aP = (mode == 3) ? *pa : 0.f;

    for (int cc = 0; cc < Cn; cc += 32) {
        // stage W chunk: 256 rows x 32 cols = 2048 float4, 8 per thread
#pragma unroll
        for (int m = 0; m < 8; m++) {
            int e4 = m * 256 + t;
            int o = e4 >> 3;
            int u4 = (e4 & 7) * 4;
            float4 v = *(const float4*)&W[(size_t)o * Cn + cc + u4];
            Ws[o * 33 + u4 + 0] = v.x;
            Ws[o * 33 + u4 + 1] = v.y;
            Ws[o * 33 + u4 + 2] = v.z;
            Ws[o * 33 + u4 + 3] = v.w;
        }
        // stage X chunk: 32 x 64
#pragma unroll
        for (int m = 0; m < 2; m++) {
            int e = m * 256 + t;
            int row = e >> 4, col = (e & 15) * 4;
            float4 v = *(const float4*)&Xb[(size_t)(cc + row) * Ln + col];
            if (mode == 3) {
                v.x = v.x >= 0.f ? v.x : aP * v.x;
                v.y = v.y >= 0.f ? v.y : aP * v.y;
                v.z = v.z >= 0.f ? v.z : aP * v.z;
                v.w = v.w >= 0.f ? v.w : aP * v.w;
            }
            *(float4*)&Xs[row][col] = v;
        }
        __syncthreads();

#pragma unroll 8
        for (int u = 0; u < 32; u++) {
            const unsigned long long* xp =
                (const unsigned long long*)&Xs[u][jb];
            unsigned long long x0 = xp[0], x1 = xp[1], x2 = xp[2], x3 = xp[3];
#pragma unroll
            for (int i = 0; i < 8; i++) {
                unsigned long long wp = pack_dup(Ws[(orow + i * 32) * 33 + u]);
                fma2(acc[i][0], wp, x0);
                fma2(acc[i][1], wp, x1);
                fma2(acc[i][2], wp, x2);
                fma2(acc[i][3], wp, x3);
            }
        }
        __syncthreads();
    }

    float* Yb = Y + ((size_t)b * Cn) * Ln + lbase;
    const float* Rb = (mode == 1) ? R + ((size_t)b * Cn) * Ln + lbase : nullptr;
#pragma unroll
    for (int i = 0; i < 8; i++) {
        int o = orow + i * 32;
        float* yp = &Yb[(size_t)o * Ln + jb];
#pragma unroll
        for (int p = 0; p < 4; p++) {
            float2 v = up2(acc[i][p]);
            if (mode == 1) {
                float2 rv = *(const float2*)&Rb[(size_t)o * Ln + jb + 2 * p];
                v.x += rv.x; v.y += rv.y;
            } else if (mode == 2) {
                float2 cur = *(float2*)&yp[2 * p];
                v.x += cur.x; v.y += cur.y;
            } else if (mode == 3) {
                v.x = fmaxf(v.x, 0.f); v.y = fmaxf(v.y, 0.f);
            }
            *(float2*)&yp[2 * p] = v;
        }
    }
}

// ---------------- launcher ---------------------------------------------------
extern "C" void kernel_launch(void* const* d_in, const int* in_sizes, int n_in,
                              void* d_out, int out_size)
{
    const float* x           = (const float*)d_in[0];
    const float* init_ln_g   = (const float*)d_in[1];
    const float* init_ln_b   = (const float*)d_in[2];
    const float* init_conv_w = (const float*)d_in[3];
    const float* w_reduce    = (const float*)d_in[4];
    const float* w_span      = (const float*)d_in[5];
    const float* prelu_a     = (const float*)d_in[6];
    const float* ln_g        = (const float*)d_in[7];
    const float* ln_b        = (const float*)d_in[8];
    const float* conv_main_w = (const float*)d_in[9];
    const float* conv_skip_w = (const float*)d_in[10];
    const float* post_prelu  = (const float*)d_in[11];
    const float* post_conv_w = (const float*)d_in[12];

    float *buf0, *buf1, *hbuf, *skip, *kern, *tmp;
    cudaGetSymbolAddress((void**)&buf0, g_buf0);
    cudaGetSymbolAddress((void**)&buf1, g_buf1);
    cudaGetSymbolAddress((void**)&hbuf, g_h);
    cudaGetSymbolAddress((void**)&skip, g_skip);
    cudaGetSymbolAddress((void**)&kern, g_kern);
    cudaGetSymbolAddress((void**)&tmp,  g_tmp);

    dim3 g32(Ln / 32, Bn);
    dim3 g64(Ln / 64, Bn);
    size_t nelem = (size_t)Bn * Cn * Ln;

    // init: LN + init conv
    ln_kernel<<<g32, 256>>>(x, init_ln_g, init_ln_b, tmp);
    gemm_kernel<<<g64, 256>>>(init_conv_w, tmp, nullptr, buf0, nullptr, 0);
    zero_kernel<<<(int)((nelem + 1023) / 1024), 1024>>>(skip, nelem);

    float* out  = buf0;
    float* outn = buf1;
    for (int i = 0; i < Nn; i++) {
        int d = 1 << (i & 7);
        kern_kernel<<<g64, 256>>>(out, w_reduce + (size_t)i * CRn * Cn,
                                  w_span + (size_t)i * Kn * CRn, kern);
        invo_kernel<<<g32, 256>>>(out, kern, prelu_a + i,
                                  ln_g + (size_t)i * Cn, ln_b + (size_t)i * Cn, d, hbuf);
        gemm_kernel<<<g64, 256>>>(conv_main_w + (size_t)i * Cn * Cn, hbuf, out, outn, nullptr, 1);
        gemm_kernel<<<g64, 256>>>(conv_skip_w + (size_t)i * Cn * Cn, hbuf, nullptr, skip, nullptr, 2);
        float* tsw = out; out = outn; outn = tsw;
    }

    // post: prelu -> conv -> relu
    gemm_kernel<<<g64, 256>>>(post_conv_w, skip, nullptr, (float*)d_out, post_prelu, 3);
}

// round 8
// speedup vs baseline: 1.4683x; 1.2669x over previous
#include <cuda_runtime.h>
#include <cuda_bf16.h>
#include <cstddef>
#include <cstdint>

#define Bn 4
#define Cn 256
#define Ln 8000
#define CRn 64
#define Kn 7
#define Nn 24
#define EPSf 1e-5f

#define NMAT 50              // 24 main + 24 skip + init(48) + post(49)
#define WELEM 65536          // 256x256 weights per matrix
#define GEMM_SMEM 92160      // bytes of dynamic smem for gemm_mma

// ---------------- scratch (device globals; no allocation allowed) ----------
__device__ float g_buf0[(size_t)Bn * Cn * Ln];
__device__ float g_buf1[(size_t)Bn * Cn * Ln];
__device__ float g_h[(size_t)Bn * Cn * Ln];
__device__ float g_skip[(size_t)Bn * Cn * Ln];
__device__ float g_kern[(size_t)Bn * Kn * Ln];
__device__ float g_tmp[(size_t)Bn * Cn * Ln];
__device__ __nv_bfloat16 g_whi[(size_t)NMAT * WELEM];
__device__ __nv_bfloat16 g_wlo[(size_t)NMAT * WELEM];

// ---------------- small helpers ---------------------------------------------
__device__ __forceinline__ uint32_t smem_u32(const void* p) {
    uint32_t a;
    asm("{ .reg .u64 t; cvta.to.shared.u64 t, %1; cvt.u32.u64 %0, t; }"
        : "=r"(a) : "l"(p));
    return a;
}
__device__ __forceinline__ void ldm4(uint32_t* r, uint32_t addr) {
    asm volatile("ldmatrix.sync.aligned.m8n8.x4.shared.b16 {%0,%1,%2,%3}, [%4];"
                 : "=r"(r[0]), "=r"(r[1]), "=r"(r[2]), "=r"(r[3]) : "r"(addr));
}
__device__ __forceinline__ void mma16816(float* c, const uint32_t* a,
                                         uint32_t b0, uint32_t b1) {
    asm volatile(
        "mma.sync.aligned.m16n8k16.row.col.f32.bf16.bf16.f32 "
        "{%0,%1,%2,%3}, {%4,%5,%6,%7}, {%8,%9}, {%10,%11,%12,%13};"
        : "=f"(c[0]), "=f"(c[1]), "=f"(c[2]), "=f"(c[3])
        : "r"(a[0]), "r"(a[1]), "r"(a[2]), "r"(a[3]), "r"(b0), "r"(b1),
          "f"(c[0]), "f"(c[1]), "f"(c[2]), "f"(c[3]));
}
__device__ __forceinline__ uint32_t pack_bf16x2(float x0, float x1) {
    __nv_bfloat16 h0 = __float2bfloat16_rn(x0);
    __nv_bfloat16 h1 = __float2bfloat16_rn(x1);
    return (uint32_t)__bfloat16_as_ushort(h0)
         | ((uint32_t)__bfloat16_as_ushort(h1) << 16);
}

// ---------------- f32x2 helpers (kern_kernel) -------------------------------
__device__ __forceinline__ unsigned long long pack_dup(float w) {
    unsigned long long r; unsigned int b = __float_as_uint(w);
    asm("mov.b64 %0, {%1, %1};" : "=l"(r) : "r"(b));
    return r;
}
__device__ __forceinline__ void fma2(unsigned long long& d,
                                     unsigned long long a, unsigned long long b) {
    asm("fma.rn.f32x2 %0, %1, %2, %3;" : "=l"(d) : "l"(a), "l"(b), "l"(d));
}
__device__ __forceinline__ float2 up2(unsigned long long v) {
    unsigned int lo, hi;
    asm("mov.b64 {%0, %1}, %2;" : "=r"(lo), "=r"(hi) : "l"(v));
    return make_float2(__uint_as_float(lo), __uint_as_float(hi));
}

// ---------------- weight prep: fp32 -> bf16 hi/lo tiles ---------------------
// layout per matrix: idx = kc*16384 + row*64 + kk, W element [row][kc*64+kk]
__global__ __launch_bounds__(256) void prep_kernel(
    const float* __restrict__ mw, const float* __restrict__ swp,
    const float* __restrict__ iw, const float* __restrict__ pw)
{
    int mat = blockIdx.x, seg = blockIdx.y;
    const float* W = (mat < 24) ? mw + (size_t)mat * Cn * Cn
                   : (mat < 48) ? swp + (size_t)(mat - 24) * Cn * Cn
                   : (mat == 48) ? iw : pw;
    size_t base = (size_t)mat * WELEM;
    for (int idx = seg * 8192 + threadIdx.x; idx < (seg + 1) * 8192; idx += 256) {
        int kk = idx & 63, row = (idx >> 6) & 255, kc = idx >> 14;
        float w = W[(size_t)row * Cn + kc * 64 + kk];
        __nv_bfloat16 hi = __float2bfloat16_rn(w);
        __nv_bfloat16 lo = __float2bfloat16_rn(w - __bfloat162float(hi));
        g_whi[base + idx] = hi;
        g_wlo[base + idx] = lo;
    }
}

// ---------------- zero ------------------------------------------------------
__global__ void zero_kernel(float* p, size_t n) {
    size_t i = (size_t)blockIdx.x * blockDim.x + threadIdx.x;
    if (i < n) p[i] = 0.f;
}

// ---------------- channel LayerNorm (over C) --------------------------------
__global__ __launch_bounds__(256) void ln_kernel(
    const float* __restrict__ x, const float* __restrict__ g,
    const float* __restrict__ bta, float* __restrict__ y)
{
    int b = blockIdx.y, lbase = blockIdx.x * 32;
    int t = threadIdx.x, j = t & 31, cg = t >> 5;
    __shared__ float vs[Cn][32];
    __shared__ float psum[8][32], psq[8][32];
    __shared__ float mres[32], rres[32];

    const float* xb = x + ((size_t)b * Cn) * Ln + lbase;
    float s = 0.f, sq = 0.f;
#pragma unroll 4
    for (int i = 0; i < 32; i++) {
        int c = cg * 32 + i;
        float v = xb[(size_t)c * Ln + j];
        vs[c][j] = v; s += v; sq += v * v;
    }
    psum[cg][j] = s; psq[cg][j] = sq;
    __syncthreads();
    if (t < 32) {
        float S = 0.f, Q = 0.f;
#pragma unroll
        for (int i = 0; i < 8; i++) { S += psum[i][t]; Q += psq[i][t]; }
        float m = S * (1.f / Cn);
        float var = Q * (1.f / Cn) - m * m;
        mres[t] = m; rres[t] = rsqrtf(var + EPSf);
    }
    __syncthreads();
    float m = mres[j], r = rres[j];
    float* yb = y + ((size_t)b * Cn) * Ln + lbase;
#pragma unroll 4
    for (int i = 0; i < 32; i++) {
        int c = cg * 32 + i;
        yb[(size_t)c * Ln + j] = (vs[c][j] - m) * r * g[c] + bta[c];
    }
}

// ---------------- involution kernel generator -------------------------------
__global__ __launch_bounds__(256) void kern_kernel(
    const float* __restrict__ out, const float* __restrict__ wr,
    const float* __restrict__ ws, float* __restrict__ kern)
{
    int b = blockIdx.y, lbase = blockIdx.x * 64;
    int t = threadIdx.x;
    __shared__ float Xs[64][64];
    __shared__ float Wr_s[64][65];
    __shared__ float rs[64][64];

    int jb = (t & 7) * 8;
    int rb = (t >> 3) * 2;

    unsigned long long acc[2][4];
#pragma unroll
    for (int i = 0; i < 2; i++)
#pragma unroll
        for (int p = 0; p < 4; p++) acc[i][p] = 0ULL;

    const float* ob = out + ((size_t)b * Cn) * Ln + lbase;

    for (int cc = 0; cc < Cn; cc += 64) {
#pragma unroll
        for (int m = 0; m < 4; m++) {
            int e4 = m * 256 + t;
            int row = e4 >> 4, col = (e4 & 15) * 4;
            *(float4*)&Xs[row][col] =
                *(const float4*)&ob[(size_t)(cc + row) * Ln + col];
        }
#pragma unroll
        for (int m = 0; m < 4; m++) {
            int e4 = m * 256 + t;
            int r = e4 >> 4, c4 = (e4 & 15) * 4;
            float4 v = *(const float4*)&wr[(size_t)r * Cn + cc + c4];
            Wr_s[r][c4 + 0] = v.x; Wr_s[r][c4 + 1] = v.y;
            Wr_s[r][c4 + 2] = v.z; Wr_s[r][c4 + 3] = v.w;
        }
        __syncthreads();

#pragma unroll 8
        for (int c = 0; c < 64; c++) {
            unsigned long long wp0 = pack_dup(Wr_s[rb][c]);
            unsigned long long wp1 = pack_dup(Wr_s[rb + 1][c]);
            const unsigned long long* xp = (const unsigned long long*)&Xs[c][jb];
            unsigned long long x0 = xp[0], x1 = xp[1], x2 = xp[2], x3 = xp[3];
            fma2(acc[0][0], wp0, x0); fma2(acc[0][1], wp0, x1);
            fma2(acc[0][2], wp0, x2); fma2(acc[0][3], wp0, x3);
            fma2(acc[1][0], wp1, x0); fma2(acc[1][1], wp1, x1);
            fma2(acc[1][2], wp1, x2); fma2(acc[1][3], wp1, x3);
        }
        __syncthreads();
    }

#pragma unroll
    for (int i = 0; i < 2; i++)
#pragma unroll
        for (int p = 0; p < 4; p++) {
            float2 v = up2(acc[i][p]);
            rs[rb + i][jb + 2 * p]     = fmaxf(v.x, 0.f);
            rs[rb + i][jb + 2 * p + 1] = fmaxf(v.y, 0.f);
        }
    __syncthreads();

    for (int kk = t; kk < Kn * 64; kk += 256) {
        int k = kk >> 6, j = kk & 63;
        float a = 0.f;
        const float* wsk = ws + (size_t)k * CRn;
#pragma unroll 8
        for (int r2 = 0; r2 < CRn; r2++) a += wsk[r2] * rs[r2][j];
        kern[((size_t)b * Kn + k) * Ln + lbase + j] = a;
    }
}

// ---------------- involution apply + PReLU + channel LN ---------------------
__global__ __launch_bounds__(256) void invo_kernel(
    const float* __restrict__ out, const float* __restrict__ kern,
    const float* __restrict__ pa, const float* __restrict__ g,
    const float* __restrict__ bta, int dil, float* __restrict__ h)
{
    int b = blockIdx.y, lbase = blockIdx.x * 32;
    int t = threadIdx.x, j = t & 31, cg = t >> 5;
    __shared__ float ks[Kn][32];
    __shared__ float hs[Cn][32];
    __shared__ float psum[8][32], psq[8][32], mres[32], rres[32];

    if (t < Kn * 32) {
        int k = t >> 5;
        ks[k][t & 31] = kern[((size_t)b * Kn + k) * Ln + lbase + (t & 31)];
    }
    __syncthreads();

    float a = *pa;
    const float* ob = out + ((size_t)b * Cn) * Ln;
    int l = lbase + j;
    float s = 0.f, sq = 0.f;
#pragma unroll 2
    for (int i = 0; i < 32; i++) {
        int c = cg * 32 + i;
        const float* oc = ob + (size_t)c * Ln;
        float acc = 0.f;
#pragma unroll
        for (int k = 0; k < Kn; k++) {
            int ll = l + (k - 3) * dil;
            float v = (ll >= 0 && ll < Ln) ? oc[ll] : 0.f;
            acc += v * ks[k][j];
        }
        acc = acc >= 0.f ? acc : a * acc;
        hs[c][j] = acc; s += acc; sq += acc * acc;
    }
    psum[cg][j] = s; psq[cg][j] = sq;
    __syncthreads();
    if (t < 32) {
        float S = 0.f, Q = 0.f;
#pragma unroll
        for (int i = 0; i < 8; i++) { S += psum[i][t]; Q += psq[i][t]; }
        float m = S * (1.f / Cn);
        mres[t] = m; rres[t] = rsqrtf(Q * (1.f / Cn) - m * m + EPSf);
    }
    __syncthreads();
    float m = mres[j], rr = rres[j];
    float* hb = h + ((size_t)b * Cn) * Ln + lbase;
#pragma unroll 4
    for (int i = 0; i < 32; i++) {
        int c = cg * 32 + i;
        hb[(size_t)c * Ln + j] = (hs[c][j] - m) * rr * g[c] + bta[c];
    }
}

// ---------------- HMMA bf16-split GEMM --------------------------------------
// Y[0..255][lbase..lbase+64) = W(mat) @ X  via mma.sync m16n8k16, bf16 2-way
// split (hi*hi + hi*lo + lo*hi), fp32 accumulate.
// CTA: 256 threads = 8 warps, warp tile 64(M) x 32(N); K=256 in 4 chunks of 64.
// smem rows padded to 72 bf16 (144B) -> ldmatrix conflict-free.
// mode 0: Y = D   1: Y = D + R   2: Y += D   3: Y = relu(D), X prelu'd on load.
__global__ __launch_bounds__(256) void gemm_mma(
    const float* __restrict__ X, const float* __restrict__ R,
    float* __restrict__ Y, int mat, const float* __restrict__ pa, int mode)
{
    extern __shared__ char smem[];
    uint16_t* Ahi = (uint16_t*)smem;          // 256 x 72
    uint16_t* Alo = Ahi + 256 * 72;           // 256 x 72
    uint16_t* Bhi = Alo + 256 * 72;           // 64 x 72  (rows = positions)
    uint16_t* Blo = Bhi + 64 * 72;            // 64 x 72

    int t = threadIdx.x, lid = t & 31, wid = t >> 5;
    int wm = wid >> 1, wn = wid & 1;          // 4 M-warps x 2 N-warps
    int b = blockIdx.y, lbase = blockIdx.x * 64;

    const float* Xb = X + (size_t)b * Cn * Ln + lbase;
    float aP = (mode == 3) ? *pa : 0.f;

    const __nv_bfloat16* Whb = g_whi + (size_t)mat * WELEM;
    const __nv_bfloat16* Wlb = g_wlo + (size_t)mat * WELEM;

    float acc[4][4][4];
#pragma unroll
    for (int i = 0; i < 4; i++)
#pragma unroll
        for (int jx = 0; jx < 4; jx++)
#pragma unroll
            for (int p = 0; p < 4; p++) acc[i][jx][p] = 0.f;

    int lr   = (lid & 7) + ((lid >> 3) & 1) * 8;   // ldmatrix row-within-16
    int koff = (lid >> 4) * 8;                      // ldmatrix k-offset
    uint32_t sbase = smem_u32(smem);

    for (int kc = 0; kc < 4; kc++) {
        // ---- stage A: 256 rows x 64 k (hi+lo), 2048 float4 each ----
        {
            const float4* shi = (const float4*)(Whb + kc * 16384);
            const float4* slo = (const float4*)(Wlb + kc * 16384);
#pragma unroll
            for (int m = 0; m < 8; m++) {
                int i = m * 256 + t;
                int row = i >> 3, q = i & 7;
                *(float4*)(Ahi + row * 72 + q * 8) = shi[i];
                *(float4*)(Alo + row * 72 + q * 8) = slo[i];
            }
        }
        // ---- stage B: X^T chunk, 64 k x 64 pos, bf16 split ----
        {
            int pos = t & 63, kp = t >> 6;
#pragma unroll
            for (int it = 0; it < 8; it++) {
                int k2 = (kp + it * 4) * 2;
                float x0 = Xb[(size_t)(kc * 64 + k2) * Ln + pos];
                float x1 = Xb[(size_t)(kc * 64 + k2 + 1) * Ln + pos];
                if (mode == 3) {
                    x0 = x0 >= 0.f ? x0 : aP * x0;
                    x1 = x1 >= 0.f ? x1 : aP * x1;
                }
                __nv_bfloat16 h0 = __float2bfloat16_rn(x0);
                __nv_bfloat16 h1 = __float2bfloat16_rn(x1);
                float r0 = x0 - __bfloat162float(h0);
                float r1 = x1 - __bfloat162float(h1);
                *(uint32_t*)(Bhi + pos * 72 + k2) =
                    (uint32_t)__bfloat16_as_ushort(h0)
                  | ((uint32_t)__bfloat16_as_ushort(h1) << 16);
                *(uint32_t*)(Blo + pos * 72 + k2) = pack_bf16x2(r0, r1);
            }
        }
        __syncthreads();

        // ---- mma over 4 k-steps of 16 ----
#pragma unroll
        for (int ks = 0; ks < 4; ks++) {
            int kcol = ks * 16 + koff;
            uint32_t bh0[4], bh1[4], bl0[4], bl1[4];
            {
                uint32_t a0 = sbase + 2 * (2 * 256 * 72) /*Bhi byte off*/;
                uint32_t ab = a0 + (uint32_t)(((wn * 32 + lr) * 72 + kcol) * 2);
                uint32_t ab2 = a0 + (uint32_t)(((wn * 32 + 16 + lr) * 72 + kcol) * 2);
                ldm4(bh0, ab);
                ldm4(bh1, ab2);
                uint32_t l0 = a0 + 64 * 72 * 2;
                ldm4(bl0, l0 + (uint32_t)(((wn * 32 + lr) * 72 + kcol) * 2));
                ldm4(bl1, l0 + (uint32_t)(((wn * 32 + 16 + lr) * 72 + kcol) * 2));
            }
#pragma unroll
            for (int mt = 0; mt < 4; mt++) {
                uint32_t ah[4], al[4];
                int arow = wm * 64 + mt * 16 + lr;
                ldm4(ah, sbase + (uint32_t)((arow * 72 + kcol) * 2));
                ldm4(al, sbase + 256 * 72 * 2 + (uint32_t)((arow * 72 + kcol) * 2));
                // ntile 0: {r0,r2} of pair0; 1: {r1,r3} of pair0; 2/3 from pair1
                mma16816(acc[mt][0], ah, bh0[0], bh0[2]);
                mma16816(acc[mt][0], ah, bl0[0], bl0[2]);
                mma16816(acc[mt][0], al, bh0[0], bh0[2]);
                mma16816(acc[mt][1], ah, bh0[1], bh0[3]);
                mma16816(acc[mt][1], ah, bl0[1], bl0[3]);
                mma16816(acc[mt][1], al, bh0[1], bh0[3]);
                mma16816(acc[mt][2], ah, bh1[0], bh1[2]);
                mma16816(acc[mt][2], ah, bl1[0], bl1[2]);
                mma16816(acc[mt][2], al, bh1[0], bh1[2]);
                mma16816(acc[mt][3], ah, bh1[1], bh1[3]);
                mma16816(acc[mt][3], ah, bl1[1], bl1[3]);
                mma16816(acc[mt][3], al, bh1[1], bh1[3]);
            }
        }
        __syncthreads();
    }

    // ---- epilogue: direct float2 stores ----
    int rbase = wm * 64 + (lid >> 2);
    int cbase = wn * 32 + (lid & 3) * 2;
#pragma unroll
    for (int mt = 0; mt < 4; mt++) {
#pragma unroll
        for (int nt = 0; nt < 4; nt++) {
            int c0 = cbase + nt * 8;
#pragma unroll
            for (int half = 0; half < 2; half++) {
                int r0 = rbase + mt * 16 + half * 8;
                float vx = acc[mt][nt][half * 2 + 0];
                float vy = acc[mt][nt][half * 2 + 1];
                float* yp = Y + ((size_t)(b * Cn + r0)) * Ln + lbase + c0;
                if (mode == 1) {
                    const float2 rv = *(const float2*)
                        (R + ((size_t)(b * Cn + r0)) * Ln + lbase + c0);
                    vx += rv.x; vy += rv.y;
                } else if (mode == 2) {
                    float2 cur = *(float2*)yp;
                    vx += cur.x; vy += cur.y;
                } else if (mode == 3) {
                    vx = fmaxf(vx, 0.f); vy = fmaxf(vy, 0.f);
                }
                float2 o; o.x = vx; o.y = vy;
                *(float2*)yp = o;
            }
        }
    }
}

// ---------------- launcher ---------------------------------------------------
extern "C" void kernel_launch(void* const* d_in, const int* in_sizes, int n_in,
                              void* d_out, int out_size)
{
    const float* x           = (const float*)d_in[0];
    const float* init_ln_g   = (const float*)d_in[1];
    const float* init_ln_b   = (const float*)d_in[2];
    const float* init_conv_w = (const float*)d_in[3];
    const float* w_reduce    = (const float*)d_in[4];
    const float* w_span      = (const float*)d_in[5];
    const float* prelu_a     = (const float*)d_in[6];
    const float* ln_g        = (const float*)d_in[7];
    const float* ln_b        = (const float*)d_in[8];
    const float* conv_main_w = (const float*)d_in[9];
    const float* conv_skip_w = (const float*)d_in[10];
    const float* post_prelu  = (const float*)d_in[11];
    const float* post_conv_w = (const float*)d_in[12];

    float *buf0, *buf1, *hbuf, *skip, *kern, *tmp;
    cudaGetSymbolAddress((void**)&buf0, g_buf0);
    cudaGetSymbolAddress((void**)&buf1, g_buf1);
    cudaGetSymbolAddress((void**)&hbuf, g_h);
    cudaGetSymbolAddress((void**)&skip, g_skip);
    cudaGetSymbolAddress((void**)&kern, g_kern);
    cudaGetSymbolAddress((void**)&tmp,  g_tmp);

    cudaFuncSetAttribute(gemm_mma, cudaFuncAttributeMaxDynamicSharedMemorySize,
                         GEMM_SMEM);

    dim3 g32(Ln / 32, Bn);
    dim3 g64(Ln / 64, Bn);
    dim3 gg(Ln / 64, Bn);
    size_t nelem = (size_t)Bn * Cn * Ln;

    prep_kernel<<<dim3(NMAT, 8), 256>>>(conv_main_w, conv_skip_w,
                                        init_conv_w, post_conv_w);
    ln_kernel<<<g32, 256>>>(x, init_ln_g, init_ln_b, tmp);
    zero_kernel<<<(int)((nelem + 1023) / 1024), 1024>>>(skip, nelem);

    // init conv: mat 48, mode 0
    gemm_mma<<<gg, 256, GEMM_SMEM>>>(tmp, nullptr, buf0, 48, nullptr, 0);

    float* out  = buf0;
    float* outn = buf1;
    for (int i = 0; i < Nn; i++) {
        int d = 1 << (i & 7);
        kern_kernel<<<g64, 256>>>(out, w_reduce + (size_t)i * CRn * Cn,
                                  w_span + (size_t)i * Kn * CRn, kern);
        invo_kernel<<<g32, 256>>>(out, kern, prelu_a + i,
                                  ln_g + (size_t)i * Cn, ln_b + (size_t)i * Cn, d, hbuf);
        gemm_mma<<<gg, 256, GEMM_SMEM>>>(hbuf, out, outn, i, nullptr, 1);
        gemm_mma<<<gg, 256, GEMM_SMEM>>>(hbuf, nullptr, skip, 24 + i, nullptr, 2);
        float* tsw = out; out = outn; outn = tsw;
    }

    // post: prelu -> conv -> relu
    gemm_mma<<<gg, 256, GEMM_SMEM>>>(skip, nullptr, (float*)d_out, 49, post_prelu, 3);
}

// round 9
// speedup vs baseline: 2.2236x; 1.5144x over previous
#include <cuda_runtime.h>
#include <cuda_bf16.h>
#include <cstddef>
#include <cstdint>

#define Bn 4
#define Cn 256
#define Ln 8000
#define CRn 64
#define Kn 7
#define Nn 24
#define EPSf 1e-5f

#define NMAT 50              // 24 main + 24 skip + init(48) + post(49)
#define WELEM 65536          // 256x256 weights per matrix
#define GEMM_SMEM 92160      // bytes of dynamic smem for gemm_mma
#define KERN_SMEM 36864      // bytes of dynamic smem for kern_mma

// ---------------- scratch (device globals; no allocation allowed) ----------
__device__ float g_buf0[(size_t)Bn * Cn * Ln];
__device__ float g_buf1[(size_t)Bn * Cn * Ln];
__device__ float g_h[(size_t)Bn * Cn * Ln];
__device__ float g_skip[(size_t)Bn * Cn * Ln];
__device__ float g_kern[(size_t)Bn * Kn * Ln];
__device__ float g_tmp[(size_t)Bn * Cn * Ln];
__device__ __nv_bfloat16 g_whi[(size_t)NMAT * WELEM];
__device__ __nv_bfloat16 g_wlo[(size_t)NMAT * WELEM];
__device__ __nv_bfloat16 g_wrhi[(size_t)Nn * CRn * Cn];
__device__ __nv_bfloat16 g_wrlo[(size_t)Nn * CRn * Cn];

// ---------------- small helpers ---------------------------------------------
__device__ __forceinline__ uint32_t smem_u32(const void* p) {
    uint32_t a;
    asm("{ .reg .u64 t; cvta.to.shared.u64 t, %1; cvt.u32.u64 %0, t; }"
        : "=r"(a) : "l"(p));
    return a;
}
__device__ __forceinline__ void ldm4(uint32_t* r, uint32_t addr) {
    asm volatile("ldmatrix.sync.aligned.m8n8.x4.shared.b16 {%0,%1,%2,%3}, [%4];"
                 : "=r"(r[0]), "=r"(r[1]), "=r"(r[2]), "=r"(r[3]) : "r"(addr));
}
__device__ __forceinline__ void mma16816(float* c, const uint32_t* a,
                                         uint32_t b0, uint32_t b1) {
    asm volatile(
        "mma.sync.aligned.m16n8k16.row.col.f32.bf16.bf16.f32 "
        "{%0,%1,%2,%3}, {%4,%5,%6,%7}, {%8,%9}, {%10,%11,%12,%13};"
        : "=f"(c[0]), "=f"(c[1]), "=f"(c[2]), "=f"(c[3])
        : "r"(a[0]), "r"(a[1]), "r"(a[2]), "r"(a[3]), "r"(b0), "r"(b1),
          "f"(c[0]), "f"(c[1]), "f"(c[2]), "f"(c[3]));
}
__device__ __forceinline__ uint32_t pack_bf16x2(float x0, float x1) {
    __nv_bfloat16 h0 = __float2bfloat16_rn(x0);
    __nv_bfloat16 h1 = __float2bfloat16_rn(x1);
    return (uint32_t)__bfloat16_as_ushort(h0)
         | ((uint32_t)__bfloat16_as_ushort(h1) << 16);
}

// ---------------- weight prep: fp32 -> bf16 hi/lo tiles ---------------------
// layout per matrix: idx = kc*16384 + row*64 + kk, W element [row][kc*64+kk]
__global__ __launch_bounds__(256) void prep_kernel(
    const float* __restrict__ mw, const float* __restrict__ swp,
    const float* __restrict__ iw, const float* __restrict__ pw)
{
    int mat = blockIdx.x, seg = blockIdx.y;
    const float* W = (mat < 24) ? mw + (size_t)mat * Cn * Cn
                   : (mat < 48) ? swp + (size_t)(mat - 24) * Cn * Cn
                   : (mat == 48) ? iw : pw;
    size_t base = (size_t)mat * WELEM;
    for (int idx = seg * 8192 + threadIdx.x; idx < (seg + 1) * 8192; idx += 256) {
        int kk = idx & 63, row = (idx >> 6) & 255, kc = idx >> 14;
        float w = W[(size_t)row * Cn + kc * 64 + kk];
        __nv_bfloat16 hi = __float2bfloat16_rn(w);
        __nv_bfloat16 lo = __float2bfloat16_rn(w - __bfloat162float(hi));
        g_whi[base + idx] = hi;
        g_wlo[base + idx] = lo;
    }
}

// wr prep: per matrix 64x256, layout idx = kc*4096 + row*64 + kk
__global__ __launch_bounds__(256) void prep_wr(const float* __restrict__ wr_all)
{
    int mat = blockIdx.x;
    const float* W = wr_all + (size_t)mat * CRn * Cn;
    size_t base = (size_t)mat * CRn * Cn;
    for (int idx = threadIdx.x; idx < CRn * Cn; idx += 256) {
        int kk = idx & 63, row = (idx >> 6) & 63, kc = idx >> 12;
        float w = W[(size_t)row * Cn + kc * 64 + kk];
        __nv_bfloat16 hi = __float2bfloat16_rn(w);
        __nv_bfloat16 lo = __float2bfloat16_rn(w - __bfloat162float(hi));
        g_wrhi[base + idx] = hi;
        g_wrlo[base + idx] = lo;
    }
}

// ---------------- zero ------------------------------------------------------
__global__ void zero_kernel(float* p, size_t n) {
    size_t i = (size_t)blockIdx.x * blockDim.x + threadIdx.x;
    if (i < n) p[i] = 0.f;
}

// ---------------- channel LayerNorm (over C) --------------------------------
__global__ __launch_bounds__(256) void ln_kernel(
    const float* __restrict__ x, const float* __restrict__ g,
    const float* __restrict__ bta, float* __restrict__ y)
{
    int b = blockIdx.y, lbase = blockIdx.x * 32;
    int t = threadIdx.x, j = t & 31, cg = t >> 5;
    __shared__ float vs[Cn][32];
    __shared__ float psum[8][32], psq[8][32];
    __shared__ float mres[32], rres[32];

    const float* xb = x + ((size_t)b * Cn) * Ln + lbase;
    float s = 0.f, sq = 0.f;
#pragma unroll 4
    for (int i = 0; i < 32; i++) {
        int c = cg * 32 + i;
        float v = xb[(size_t)c * Ln + j];
        vs[c][j] = v; s += v; sq += v * v;
    }
    psum[cg][j] = s; psq[cg][j] = sq;
    __syncthreads();
    if (t < 32) {
        float S = 0.f, Q = 0.f;
#pragma unroll
        for (int i = 0; i < 8; i++) { S += psum[i][t]; Q += psq[i][t]; }
        float m = S * (1.f / Cn);
        float var = Q * (1.f / Cn) - m * m;
        mres[t] = m; rres[t] = rsqrtf(var + EPSf);
    }
    __syncthreads();
    float m = mres[j], r = rres[j];
    float* yb = y + ((size_t)b * Cn) * Ln + lbase;
#pragma unroll 4
    for (int i = 0; i < 32; i++) {
        int c = cg * 32 + i;
        yb[(size_t)c * Ln + j] = (vs[c][j] - m) * r * g[c] + bta[c];
    }
}

// ---------------- involution kernel generator (HMMA) ------------------------
// kern = Ws @ relu(Wr @ out); reduce GEMM M=64 x N=64pos x K=256 via bf16-split
// mma; span stays scalar. grid (L/64, B), 256 threads = 8 warps (2M x 4N).
__global__ __launch_bounds__(256) void kern_mma(
    const float* __restrict__ out, const float* __restrict__ ws,
    int mat, float* __restrict__ kern)
{
    extern __shared__ char ksm[];
    uint16_t* Ahi = (uint16_t*)ksm;        // 64 x 72
    uint16_t* Alo = Ahi + 64 * 72;         // 64 x 72
    uint16_t* Bhi = Alo + 64 * 72;         // 64 x 72 (rows = positions)
    uint16_t* Blo = Bhi + 64 * 72;         // 64 x 72
    float* rs = (float*)ksm;               // aliased after mma: 64 x 65

    int t = threadIdx.x, lid = t & 31, wid = t >> 5;
    int wm = wid >> 2, wn = wid & 3;       // 2 M-warps x 4 N-warps
    int b = blockIdx.y, lbase = blockIdx.x * 64;
    const float* Xb = out + (size_t)b * Cn * Ln + lbase;
    const __nv_bfloat16* Wh = g_wrhi + (size_t)mat * CRn * Cn;
    const __nv_bfloat16* Wl = g_wrlo + (size_t)mat * CRn * Cn;

    float acc[2][2][4];
#pragma unroll
    for (int i = 0; i < 2; i++)
#pragma unroll
        for (int jx = 0; jx < 2; jx++)
#pragma unroll
            for (int p = 0; p < 4; p++) acc[i][jx][p] = 0.f;

    int lr   = (lid & 7) + ((lid >> 3) & 1) * 8;
    int koff = (lid >> 4) * 8;
    uint32_t sbase = smem_u32(ksm);

    for (int kc = 0; kc < 4; kc++) {
        // stage A: 64 rows x 64 k (hi+lo) = 512 float4 each
        {
            const float4* shi = (const float4*)(Wh + kc * 4096);
            const float4* slo = (const float4*)(Wl + kc * 4096);
#pragma unroll
            for (int m = 0; m < 2; m++) {
                int i = m * 256 + t;
                int row = i >> 3, q = i & 7;
                *(float4*)(Ahi + row * 72 + q * 8) = shi[i];
                *(float4*)(Alo + row * 72 + q * 8) = slo[i];
            }
        }
        // stage B: X^T chunk 64k x 64 pos, bf16 split
        {
            int pos = t & 63, kp = t >> 6;
#pragma unroll
            for (int it = 0; it < 8; it++) {
                int k2 = (kp + it * 4) * 2;
                float x0 = Xb[(size_t)(kc * 64 + k2) * Ln + pos];
                float x1 = Xb[(size_t)(kc * 64 + k2 + 1) * Ln + pos];
                __nv_bfloat16 h0 = __float2bfloat16_rn(x0);
                __nv_bfloat16 h1 = __float2bfloat16_rn(x1);
                *(uint32_t*)(Bhi + pos * 72 + k2) =
                    (uint32_t)__bfloat16_as_ushort(h0)
                  | ((uint32_t)__bfloat16_as_ushort(h1) << 16);
                *(uint32_t*)(Blo + pos * 72 + k2) =
                    pack_bf16x2(x0 - __bfloat162float(h0),
                                x1 - __bfloat162float(h1));
            }
        }
        __syncthreads();

#pragma unroll
        for (int ks = 0; ks < 4; ks++) {
            int kcol = ks * 16 + koff;
            uint32_t bh[4], bl[4];
            uint32_t bb = sbase + 2 * (2 * 64 * 72);      // Bhi byte offset
            ldm4(bh, bb + (uint32_t)(((wn * 16 + lr) * 72 + kcol) * 2));
            ldm4(bl, bb + 64 * 72 * 2
                     + (uint32_t)(((wn * 16 + lr) * 72 + kcol) * 2));
#pragma unroll
            for (int mt = 0; mt < 2; mt++) {
                uint32_t ah[4], al[4];
                int arow = wm * 32 + mt * 16 + lr;
                ldm4(ah, sbase + (uint32_t)((arow * 72 + kcol) * 2));
                ldm4(al, sbase + 64 * 72 * 2
                         + (uint32_t)((arow * 72 + kcol) * 2));
                mma16816(acc[mt][0], ah, bh[0], bh[2]);
                mma16816(acc[mt][0], ah, bl[0], bl[2]);
                mma16816(acc[mt][0], al, bh[0], bh[2]);
                mma16816(acc[mt][1], ah, bh[1], bh[3]);
                mma16816(acc[mt][1], ah, bl[1], bl[3]);
                mma16816(acc[mt][1], al, bh[1], bh[3]);
            }
        }
        __syncthreads();
    }

    // relu -> rs (alias over A/B; all smem reads done)
    {
        int r0 = wm * 32 + (lid >> 2), c0 = wn * 16 + (lid & 3) * 2;
#pragma unroll
        for (int mt = 0; mt < 2; mt++)
#pragma unroll
            for (int nt = 0; nt < 2; nt++)
#pragma unroll
                for (int half = 0; half < 2; half++) {
                    int r = r0 + mt * 16 + half * 8;
                    int c = c0 + nt * 8;
                    rs[r * 65 + c]     = fmaxf(acc[mt][nt][half * 2 + 0], 0.f);
                    rs[r * 65 + c + 1] = fmaxf(acc[mt][nt][half * 2 + 1], 0.f);
                }
    }
    __syncthreads();

    // span: 7 x 64 outputs
    for (int kk = t; kk < Kn * 64; kk += 256) {
        int k = kk >> 6, j = kk & 63;
        float a = 0.f;
        const float* wsk = ws + (size_t)k * CRn;
#pragma unroll 8
        for (int r2 = 0; r2 < CRn; r2++) a += wsk[r2] * rs[r2 * 65 + j];
        kern[((size_t)b * Kn + k) * Ln + lbase + j] = a;
    }
}

// ---------------- involution apply + PReLU + channel LN ---------------------
__global__ __launch_bounds__(256) void invo_kernel(
    const float* __restrict__ out, const float* __restrict__ kern,
    const float* __restrict__ pa, const float* __restrict__ g,
    const float* __restrict__ bta, int dil, float* __restrict__ h)
{
    int b = blockIdx.y, lbase = blockIdx.x * 32;
    int t = threadIdx.x, j = t & 31, cg = t >> 5;
    __shared__ float ks[Kn][32];
    __shared__ float hs[Cn][32];
    __shared__ float psum[8][32], psq[8][32], mres[32], rres[32];

    if (t < Kn * 32) {
        int k = t >> 5;
        ks[k][t & 31] = kern[((size_t)b * Kn + k) * Ln + lbase + (t & 31)];
    }
    __syncthreads();

    float a = *pa;
    const float* ob = out + ((size_t)b * Cn) * Ln;
    int l = lbase + j;
    float s = 0.f, sq = 0.f;
#pragma unroll 2
    for (int i = 0; i < 32; i++) {
        int c = cg * 32 + i;
        const float* oc = ob + (size_t)c * Ln;
        float acc = 0.f;
#pragma unroll
        for (int k = 0; k < Kn; k++) {
            int ll = l + (k - 3) * dil;
            float v = (ll >= 0 && ll < Ln) ? oc[ll] : 0.f;
            acc += v * ks[k][j];
        }
        acc = acc >= 0.f ? acc : a * acc;
        hs[c][j] = acc; s += acc; sq += acc * acc;
    }
    psum[cg][j] = s; psq[cg][j] = sq;
    __syncthreads();
    if (t < 32) {
        float S = 0.f, Q = 0.f;
#pragma unroll
        for (int i = 0; i < 8; i++) { S += psum[i][t]; Q += psq[i][t]; }
        float m = S * (1.f / Cn);
        mres[t] = m; rres[t] = rsqrtf(Q * (1.f / Cn) - m * m + EPSf);
    }
    __syncthreads();
    float m = mres[j], rr = rres[j];
    float* hb = h + ((size_t)b * Cn) * Ln + lbase;
#pragma unroll 4
    for (int i = 0; i < 32; i++) {
        int c = cg * 32 + i;
        hb[(size_t)c * Ln + j] = (hs[c][j] - m) * rr * g[c] + bta[c];
    }
}

// ---------------- HMMA bf16-split GEMM --------------------------------------
// Y[0..255][lbase..lbase+64) = W(mat) @ X via mma.sync m16n8k16, bf16 2-way
// split (hi*hi + hi*lo + lo*hi), fp32 accumulate.
// CTA: 256 threads = 8 warps, warp tile 64(M) x 32(N); K=256 in 4 chunks of 64.
// launch_bounds(256,2): cap regs at 128 so 2 CTAs co-reside per SM.
// mode 0: Y = D   1: Y = D + R   2: Y += D   3: Y = relu(D), X prelu'd on load.
__global__ __launch_bounds__(256, 2) void gemm_mma(
    const float* __restrict__ X, const float* __restrict__ R,
    float* __restrict__ Y, int mat, const float* __restrict__ pa, int mode)
{
    extern __shared__ char smem[];
    uint16_t* Ahi = (uint16_t*)smem;          // 256 x 72
    uint16_t* Alo = Ahi + 256 * 72;           // 256 x 72
    uint16_t* Bhi = Alo + 256 * 72;           // 64 x 72  (rows = positions)
    uint16_t* Blo = Bhi + 64 * 72;            // 64 x 72

    int t = threadIdx.x, lid = t & 31, wid = t >> 5;
    int wm = wid >> 1, wn = wid & 1;          // 4 M-warps x 2 N-warps
    int b = blockIdx.y, lbase = blockIdx.x * 64;

    const float* Xb = X + (size_t)b * Cn * Ln + lbase;
    float aP = (mode == 3) ? *pa : 0.f;

    const __nv_bfloat16* Whb = g_whi + (size_t)mat * WELEM;
    const __nv_bfloat16* Wlb = g_wlo + (size_t)mat * WELEM;

    float acc[4][4][4];
#pragma unroll
    for (int i = 0; i < 4; i++)
#pragma unroll
        for (int jx = 0; jx < 4; jx++)
#pragma unroll
            for (int p = 0; p < 4; p++) acc[i][jx][p] = 0.f;

    int lr   = (lid & 7) + ((lid >> 3) & 1) * 8;   // ldmatrix row-within-16
    int koff = (lid >> 4) * 8;                      // ldmatrix k-offset
    uint32_t sbase = smem_u32(smem);

    for (int kc = 0; kc < 4; kc++) {
        // ---- stage A: 256 rows x 64 k (hi+lo), 2048 float4 each ----
        {
            const float4* shi = (const float4*)(Whb + kc * 16384);
            const float4* slo = (const float4*)(Wlb + kc * 16384);
#pragma unroll
            for (int m = 0; m < 8; m++) {
                int i = m * 256 + t;
                int row = i >> 3, q = i & 7;
                *(float4*)(Ahi + row * 72 + q * 8) = shi[i];
                *(float4*)(Alo + row * 72 + q * 8) = slo[i];
            }
        }
        // ---- stage B: X^T chunk, 64 k x 64 pos, bf16 split ----
        {
            int pos = t & 63, kp = t >> 6;
#pragma unroll
            for (int it = 0; it < 8; it++) {
                int k2 = (kp + it * 4) * 2;
                float x0 = Xb[(size_t)(kc * 64 + k2) * Ln + pos];
                float x1 = Xb[(size_t)(kc * 64 + k2 + 1) * Ln + pos];
                if (mode == 3) {
                    x0 = x0 >= 0.f ? x0 : aP * x0;
                    x1 = x1 >= 0.f ? x1 : aP * x1;
                }
                __nv_bfloat16 h0 = __float2bfloat16_rn(x0);
                __nv_bfloat16 h1 = __float2bfloat16_rn(x1);
                float r0 = x0 - __bfloat162float(h0);
                float r1 = x1 - __bfloat162float(h1);
                *(uint32_t*)(Bhi + pos * 72 + k2) =
                    (uint32_t)__bfloat16_as_ushort(h0)
                  | ((uint32_t)__bfloat16_as_ushort(h1) << 16);
                *(uint32_t*)(Blo + pos * 72 + k2) = pack_bf16x2(r0, r1);
            }
        }
        __syncthreads();

        // ---- mma over 4 k-steps of 16 ----
#pragma unroll
        for (int ks = 0; ks < 4; ks++) {
            int kcol = ks * 16 + koff;
            uint32_t bh0[4], bh1[4], bl0[4], bl1[4];
            {
                uint32_t a0 = sbase + 2 * (2 * 256 * 72) /*Bhi byte off*/;
                uint32_t ab = a0 + (uint32_t)(((wn * 32 + lr) * 72 + kcol) * 2);
                uint32_t ab2 = a0 + (uint32_t)(((wn * 32 + 16 + lr) * 72 + kcol) * 2);
                ldm4(bh0, ab);
                ldm4(bh1, ab2);
                uint32_t l0 = a0 + 64 * 72 * 2;
                ldm4(bl0, l0 + (uint32_t)(((wn * 32 + lr) * 72 + kcol) * 2));
                ldm4(bl1, l0 + (uint32_t)(((wn * 32 + 16 + lr) * 72 + kcol) * 2));
            }
#pragma unroll
            for (int mt = 0; mt < 4; mt++) {
                uint32_t ah[4], al[4];
                int arow = wm * 64 + mt * 16 + lr;
                ldm4(ah, sbase + (uint32_t)((arow * 72 + kcol) * 2));
                ldm4(al, sbase + 256 * 72 * 2 + (uint32_t)((arow * 72 + kcol) * 2));
                mma16816(acc[mt][0], ah, bh0[0], bh0[2]);
                mma16816(acc[mt][0], ah, bl0[0], bl0[2]);
                mma16816(acc[mt][0], al, bh0[0], bh0[2]);
                mma16816(acc[mt][1], ah, bh0[1], bh0[3]);
                mma16816(acc[mt][1], ah, bl0[1], bl0[3]);
                mma16816(acc[mt][1], al, bh0[1], bh0[3]);
                mma16816(acc[mt][2], ah, bh1[0], bh1[2]);
                mma16816(acc[mt][2], ah, bl1[0], bl1[2]);
                mma16816(acc[mt][2], al, bh1[0], bh1[2]);
                mma16816(acc[mt][3], ah, bh1[1], bh1[3]);
                mma16816(acc[mt][3], ah, bl1[1], bl1[3]);
                mma16816(acc[mt][3], al, bh1[1], bh1[3]);
            }
        }
        __syncthreads();
    }

    // ---- epilogue: direct float2 stores ----
    int rbase = wm * 64 + (lid >> 2);
    int cbase = wn * 32 + (lid & 3) * 2;
#pragma unroll
    for (int mt = 0; mt < 4; mt++) {
#pragma unroll
        for (int nt = 0; nt < 4; nt++) {
            int c0 = cbase + nt * 8;
#pragma unroll
            for (int half = 0; half < 2; half++) {
                int r0 = rbase + mt * 16 + half * 8;
                float vx = acc[mt][nt][half * 2 + 0];
                float vy = acc[mt][nt][half * 2 + 1];
                float* yp = Y + ((size_t)(b * Cn + r0)) * Ln + lbase + c0;
                if (mode == 1) {
                    const float2 rv = *(const float2*)
                        (R + ((size_t)(b * Cn + r0)) * Ln + lbase + c0);
                    vx += rv.x; vy += rv.y;
                } else if (mode == 2) {
                    float2 cur = *(float2*)yp;
                    vx += cur.x; vy += cur.y;
                } else if (mode == 3) {
                    vx = fmaxf(vx, 0.f); vy = fmaxf(vy, 0.f);
                }
                float2 o; o.x = vx; o.y = vy;
                *(float2*)yp = o;
            }
        }
    }
}

// ---------------- launcher ---------------------------------------------------
extern "C" void kernel_launch(void* const* d_in, const int* in_sizes, int n_in,
                              void* d_out, int out_size)
{
    const float* x           = (const float*)d_in[0];
    const float* init_ln_g   = (const float*)d_in[1];
    const float* init_ln_b   = (const float*)d_in[2];
    const float* init_conv_w = (const float*)d_in[3];
    const float* w_reduce    = (const float*)d_in[4];
    const float* w_span      = (const float*)d_in[5];
    const float* prelu_a     = (const float*)d_in[6];
    const float* ln_g        = (const float*)d_in[7];
    const float* ln_b        = (const float*)d_in[8];
    const float* conv_main_w = (const float*)d_in[9];
    const float* conv_skip_w = (const float*)d_in[10];
    const float* post_prelu  = (const float*)d_in[11];
    const float* post_conv_w = (const float*)d_in[12];

    float *buf0, *buf1, *hbuf, *skip, *kern, *tmp;
    cudaGetSymbolAddress((void**)&buf0, g_buf0);
    cudaGetSymbolAddress((void**)&buf1, g_buf1);
    cudaGetSymbolAddress((void**)&hbuf, g_h);
    cudaGetSymbolAddress((void**)&skip, g_skip);
    cudaGetSymbolAddress((void**)&kern, g_kern);
    cudaGetSymbolAddress((void**)&tmp,  g_tmp);

    cudaFuncSetAttribute(gemm_mma, cudaFuncAttributeMaxDynamicSharedMemorySize,
                         GEMM_SMEM);

    dim3 g32(Ln / 32, Bn);
    dim3 g64(Ln / 64, Bn);
    dim3 gg(Ln / 64, Bn);
    size_t nelem = (size_t)Bn * Cn * Ln;

    prep_kernel<<<dim3(NMAT, 8), 256>>>(conv_main_w, conv_skip_w,
                                        init_conv_w, post_conv_w);
    prep_wr<<<Nn, 256>>>(w_reduce);
    ln_kernel<<<g32, 256>>>(x, init_ln_g, init_ln_b, tmp);
    zero_kernel<<<(int)((nelem + 1023) / 1024), 1024>>>(skip, nelem);

    // init conv: mat 48, mode 0
    gemm_mma<<<gg, 256, GEMM_SMEM>>>(tmp, nullptr, buf0, 48, nullptr, 0);

    float* out  = buf0;
    float* outn = buf1;
    for (int i = 0; i < Nn; i++) {
        int d = 1 << (i & 7);
        kern_mma<<<g64, 256, KERN_SMEM>>>(out, w_span + (size_t)i * Kn * CRn,
                                          i, kern);
        invo_kernel<<<g32, 256>>>(out, kern, prelu_a + i,
                                  ln_g + (size_t)i * Cn, ln_b + (size_t)i * Cn, d, hbuf);
        gemm_mma<<<gg, 256, GEMM_SMEM>>>(hbuf, out, outn, i, nullptr, 1);
        gemm_mma<<<gg, 256, GEMM_SMEM>>>(hbuf, nullptr, skip, 24 + i, nullptr, 2);
        float* tsw = out; out = outn; outn = tsw;
    }

    // post: prelu -> conv -> relu
    gemm_mma<<<gg, 256, GEMM_SMEM>>>(skip, nullptr, (float*)d_out, 49, post_prelu, 3);
}